// round 8
// baseline (speedup 1.0000x reference)
#include <cuda_runtime.h>
#include <math.h>
#include <stdint.h>

#define HIDD 128
#define KTOT 256
#define NMAX 100352
#define EMAX 602112

// ---------------- scratch (device globals; no allocation allowed) ----------
__device__ int   g_cnt[NMAX];
__device__ int   g_incl[NMAX];
__device__ int   g_bsum[256];
__device__ int   g_boff[256];
__device__ int   g_rowptr[NMAX + 1];
__device__ int   g_wpos[NMAX];
__device__ int   g_csr[EMAX];
__device__ float g_mean[(size_t)NMAX * HIDD];
__device__ float g_h0[(size_t)NMAX * HIDD];
__device__ float g_bnsum[HIDD];
__device__ float g_bnss[HIDD];
__device__ float g_scale[HIDD];
__device__ float g_shift[HIDD];
// B fragments: [layer][ (chunk16*16+ntile)*2+part ][64]  (uint32 bf16x2 pairs)
__device__ uint32_t g_Bfrag[2][16 * 16 * 2 * 64];
__device__ float g_bias2[HIDD];

// ---------------- helpers ---------------------------------------------------
__device__ __forceinline__ float bf16rd(float x) {
    float r;
    asm("{.reg .b16 t; cvt.rn.bf16.f32 t, %1; cvt.f32.bf16 %0, t;}"
        : "=f"(r) : "f"(x));
    return r;
}
// pack: e0 -> low 16 bits, e1 -> high 16 bits (PTX: first src = upper half)
__device__ __forceinline__ uint32_t pack2(float e0, float e1) {
    uint32_t r;
    asm("cvt.rn.bf16x2.f32 %0, %1, %2;" : "=r"(r) : "f"(e1), "f"(e0));
    return r;
}
__device__ __forceinline__ uint32_t smem_u32(const void* p) {
    uint32_t a;
    asm("{ .reg .u64 t; cvta.to.shared.u64 t, %1; cvt.u32.u64 %0, t; }"
        : "=r"(a) : "l"(p));
    return a;
}
__device__ __forceinline__ void ldm4(uint32_t* r, uint32_t addr) {
    asm volatile(
        "ldmatrix.sync.aligned.m8n8.x4.shared.b16 {%0,%1,%2,%3}, [%4];"
        : "=r"(r[0]), "=r"(r[1]), "=r"(r[2]), "=r"(r[3]) : "r"(addr));
}
__device__ __forceinline__ void mma16(float* c, const uint32_t* a, uint32_t b0,
                                      uint32_t b1) {
    asm volatile(
        "mma.sync.aligned.m16n8k16.row.col.f32.bf16.bf16.f32 "
        "{%0,%1,%2,%3},{%4,%5,%6,%7},{%8,%9},{%0,%1,%2,%3};"
        : "+f"(c[0]), "+f"(c[1]), "+f"(c[2]), "+f"(c[3])
        : "r"(a[0]), "r"(a[1]), "r"(a[2]), "r"(a[3]), "r"(b0), "r"(b1));
}

// ---------------- small kernels --------------------------------------------
__global__ void k_zero(int n) {
    int i = blockIdx.x * blockDim.x + threadIdx.x;
    if (i < n) g_cnt[i] = 0;
    if (i < HIDD) { g_bnsum[i] = 0.f; g_bnss[i] = 0.f; }
}
__global__ void k_hist(const int* __restrict__ dst, int E) {
    int e = blockIdx.x * blockDim.x + threadIdx.x;
    if (e < E) atomicAdd(&g_cnt[dst[e]], 1);
}
__global__ void k_scan1(int n) {
    __shared__ int s[1024];
    int t = threadIdx.x;
    int i = blockIdx.x * 1024 + t;
    int v = (i < n) ? g_cnt[i] : 0;
    s[t] = v;
    __syncthreads();
    for (int off = 1; off < 1024; off <<= 1) {
        int x = (t >= off) ? s[t - off] : 0;
        __syncthreads();
        s[t] += x;
        __syncthreads();
    }
    if (i < n) g_incl[i] = s[t];
    if (t == 1023) g_bsum[blockIdx.x] = s[1023];
}
__global__ void k_scan2(int nb) {
    __shared__ int s[128];
    int t = threadIdx.x;
    int v = (t < nb) ? g_bsum[t] : 0;
    s[t] = v;
    __syncthreads();
    for (int off = 1; off < 128; off <<= 1) {
        int x = (t >= off) ? s[t - off] : 0;
        __syncthreads();
        s[t] += x;
        __syncthreads();
    }
    if (t < nb) g_boff[t] = s[t] - v;
}
__global__ void k_scan3(int n, int E) {
    int i = blockIdx.x * blockDim.x + threadIdx.x;
    if (i < n) {
        int excl = g_incl[i] - g_cnt[i] + g_boff[i >> 10];
        g_rowptr[i] = excl;
        g_wpos[i] = excl;
        if (i == 0) g_rowptr[n] = E;
    }
}
__global__ void k_fill(const int* __restrict__ src, const int* __restrict__ dst, int E) {
    int e = blockIdx.x * blockDim.x + threadIdx.x;
    if (e < E) {
        int d = dst[e];
        int p = atomicAdd(&g_wpos[d], 1);
        g_csr[p] = src[e];
    }
}

// weight -> bf16 hi/lo b-fragments for m16n8k16 row.col
__global__ void k_prepw(const float* __restrict__ Wl, const float* __restrict__ Wr,
                        int layer, int useScale) {
    int idx = blockIdx.x * 256 + threadIdx.x;  // 16384 total
    int reg = idx & 1;
    int lane = (idx >> 1) & 31;
    int ntile = (idx >> 6) & 15;
    int chunk = idx >> 10;
    int tig = lane & 3, gcol = lane >> 2;
    int nn = ntile * 8 + gcol;
    int k0 = chunk * 16 + reg * 8 + tig * 2;
    int k1 = k0 + 1;
    float w0 = (k0 < HIDD) ? Wl[k0 * HIDD + nn] : Wr[(k0 - HIDD) * HIDD + nn];
    float w1 = (k1 < HIDD) ? Wl[k1 * HIDD + nn] : Wr[(k1 - HIDD) * HIDD + nn];
    if (useScale && k0 >= HIDD) {
        w0 *= g_scale[k0 - HIDD];
        w1 *= g_scale[k1 - HIDD];
    }
    float h0 = bf16rd(w0), h1 = bf16rd(w1);
    int base = ((chunk * 16 + ntile) * 2) * 64 + lane * 2 + reg;
    g_Bfrag[layer][base] = pack2(w0, w1);
    g_Bfrag[layer][base + 64] = pack2(w0 - h0, w1 - h1);
}

// bias2[n] = b2l[n] + sum_j shift[j] * W2r[j][n]
__global__ void k_bias2(const float* __restrict__ b2l, const float* __restrict__ W2r) {
    int nn = threadIdx.x;
    float s = b2l[nn];
    for (int j = 0; j < HIDD; j++) s += g_shift[j] * W2r[j * HIDD + nn];
    g_bias2[nn] = s;
}

// BN column sums over h0
__global__ void k_bnstat(const float* __restrict__ h0, int n) {
    __shared__ float s1[128], s2[128];
    int t = threadIdx.x;
    int col = t & 127;
    int half = t >> 7;
    float s = 0.f, q = 0.f;
    int base = blockIdx.x * 256;
    for (int i = half; i < 256; i += 2) {
        int r = base + i;
        if (r < n) {
            float v = h0[(size_t)r * HIDD + col];
            s += v; q += v * v;
        }
    }
    if (half == 0) { s1[col] = s; s2[col] = q; }
    __syncthreads();
    if (half == 1) { s1[col] += s; s2[col] += q; }
    __syncthreads();
    if (t < 128) {
        atomicAdd(&g_bnsum[t], s1[t]);
        atomicAdd(&g_bnss[t], s2[t]);
    }
}

__global__ void k_bnfin(const float* __restrict__ gamma, const float* __restrict__ beta,
                        int n) {
    int c = threadIdx.x;
    if (c < HIDD) {
        float mu = g_bnsum[c] / (float)n;
        float var = g_bnss[c] / (float)n - mu * mu;
        float sc = gamma[c] * rsqrtf(var + 1e-5f);
        g_scale[c] = sc;
        g_shift[c] = beta[c] - mu * sc;
    }
}

// ---------------- aggregation: one warp per node, 4-way unroll --------------
__global__ void k_agg(const float* __restrict__ feat, float* __restrict__ outm,
                      int n, int layer2) {
    int w = (blockIdx.x * blockDim.x + threadIdx.x) >> 5;
    int lane = threadIdx.x & 31;
    if (w >= n) return;
    int r0 = g_rowptr[w], r1 = g_rowptr[w + 1];
    const float4* f4 = (const float4*)feat;
    float4 a = make_float4(0.f, 0.f, 0.f, 0.f);
    int j = r0;
    for (; j + 3 < r1; j += 4) {
        int s0 = g_csr[j];
        int s1 = g_csr[j + 1];
        int s2 = g_csr[j + 2];
        int s3 = g_csr[j + 3];
        float4 v0 = f4[(size_t)s0 * 32 + lane];
        float4 v1 = f4[(size_t)s1 * 32 + lane];
        float4 v2 = f4[(size_t)s2 * 32 + lane];
        float4 v3 = f4[(size_t)s3 * 32 + lane];
        a.x += v0.x + v1.x + v2.x + v3.x;
        a.y += v0.y + v1.y + v2.y + v3.y;
        a.z += v0.z + v1.z + v2.z + v3.z;
        a.w += v0.w + v1.w + v2.w + v3.w;
    }
    for (; j < r1; j++) {
        int s0 = g_csr[j];
        float4 v0 = f4[(size_t)s0 * 32 + lane];
        a.x += v0.x; a.y += v0.y; a.z += v0.z; a.w += v0.w;
    }
    int deg = r1 - r0;
    float inv = (deg > 0) ? 1.f / (float)deg : 0.f;
    float4 m = make_float4(a.x * inv, a.y * inv, a.z * inv, a.w * inv);
    if (layer2) {
        if (deg > 0) {
            float4 sc = *(const float4*)(g_scale + lane * 4);
            float4 sh = *(const float4*)(g_shift + lane * 4);
            m.x = m.x * sc.x + sh.x; m.y = m.y * sc.y + sh.y;
            m.z = m.z * sc.z + sh.z; m.w = m.w * sc.w + sh.w;
        } else {
            m = make_float4(0.f, 0.f, 0.f, 0.f);
        }
    }
    ((float4*)outm)[(size_t)w * 32 + lane] = m;
}

// ---------------- GEMM via bf16 m16n8k16 mma (3-term compensation) ----------
// Block: 128 rows x 128 cols x K=256, 256 threads = 8 warps (4 mrow x 2 ncol).
// Warp covers rows wrow*32..+31 (2 x m16), cols wcol*64..+63 (8 x n8).
template <int LAYER>
__global__ __launch_bounds__(256, 2) void k_mma(
    const float* __restrict__ meanbuf, const float* __restrict__ featbuf,
    const float* __restrict__ bias, const float* __restrict__ fcW,
    const float* __restrict__ fcb, float* __restrict__ outbuf,
    float* __restrict__ predout, int n) {
    __shared__ __align__(16) uint32_t sA[2][2][128 * 12];  // [buf][part][row*12+pair]
    __shared__ float s_bias[128];
    __shared__ float s_fcw[64];
    __shared__ float s_ssq[128][2];

    const int t = threadIdx.x;
    const int wid = t >> 5, lane = t & 31;
    const int wrow = wid >> 1, wcol = wid & 1;
    const int mtile = blockIdx.x * 128;

    if (t < 128) s_bias[t] = bias[t];
    if (LAYER == 2 && t < 64) s_fcw[t] = fcW[t];

    float acc[2][8][4];
#pragma unroll
    for (int ms = 0; ms < 2; ms++)
#pragma unroll
        for (int nt = 0; nt < 8; nt++)
#pragma unroll
            for (int j = 0; j < 4; j++) acc[ms][nt][j] = 0.f;

    const uint32_t* __restrict__ Bf = g_Bfrag[LAYER - 1];

    const int srow = t >> 1;       // staged row (0..127)
    const int kh = t & 1;          // k half (0 or 1) -> 8 floats
    const uint32_t sAb = smem_u32(&sA[0][0][0]);
    const int lrow = lane & 15;
    const int kpair = (lane >> 4) * 4;  // uint32 offset for k 8..15 matrices

    // prefetch chunk 0
    float4 av0 = make_float4(0.f, 0.f, 0.f, 0.f), av1 = av0;
    {
        int m = mtile + srow;
        if (m < n) {
            const float* p = meanbuf + (size_t)m * HIDD + kh * 8;
            av0 = *(const float4*)p;
            av1 = *(const float4*)(p + 4);
        }
    }

    for (int chunk = 0; chunk < 16; chunk++) {
        const int buf = chunk & 1;
        // ---- stage A chunk (all 256 threads) ----
        {
            float f[8] = {av0.x, av0.y, av0.z, av0.w, av1.x, av1.y, av1.z, av1.w};
            uint32_t hp[4], lp[4];
#pragma unroll
            for (int p = 0; p < 4; p++) {
                float e0 = f[2 * p], e1 = f[2 * p + 1];
                float h0 = bf16rd(e0), h1 = bf16rd(e1);
                hp[p] = pack2(e0, e1);
                lp[p] = pack2(e0 - h0, e1 - h1);
            }
            uint32_t* d0 = &sA[buf][0][srow * 12 + kh * 4];
            uint32_t* d1 = &sA[buf][1][srow * 12 + kh * 4];
            *(uint4*)d0 = make_uint4(hp[0], hp[1], hp[2], hp[3]);
            *(uint4*)d1 = make_uint4(lp[0], lp[1], lp[2], lp[3]);
        }
        __syncthreads();
        // ---- prefetch next chunk ----
        if (chunk < 15) {
            int c1 = chunk + 1;
            const float* src = (c1 < 8) ? meanbuf : featbuf;
            int kc = (c1 & 7) * 16 + kh * 8;
            int m = mtile + srow;
            if (m < n) {
                const float* p = src + (size_t)m * HIDD + kc;
                av0 = *(const float4*)p;
                av1 = *(const float4*)(p + 4);
            } else {
                av0 = make_float4(0.f, 0.f, 0.f, 0.f);
                av1 = av0;
            }
        }
        // ---- A fragments via ldmatrix ----
        uint32_t Ah[2][4], Al[2][4];
#pragma unroll
        for (int ms = 0; ms < 2; ms++) {
            int r = wrow * 32 + ms * 16 + lrow;
            uint32_t off = (uint32_t)(r * 12 + kpair) * 4u;
            ldm4(Ah[ms], sAb + buf * 12288u + off);
            ldm4(Al[ms], sAb + buf * 12288u + 6144u + off);
        }
        // ---- B hi fragments: hh + lh products ----
        uint32_t Bh[8][2];
#pragma unroll
        for (int nt = 0; nt < 8; nt++) {
            const uint32_t* bp =
                Bf + ((size_t)(chunk * 16 + wcol * 8 + nt) * 2) * 64 + lane * 2;
            Bh[nt][0] = bp[0];
            Bh[nt][1] = bp[1];
        }
#pragma unroll
        for (int ms = 0; ms < 2; ms++)
#pragma unroll
            for (int nt = 0; nt < 8; nt++) {
                mma16(acc[ms][nt], Ah[ms], Bh[nt][0], Bh[nt][1]);
                mma16(acc[ms][nt], Al[ms], Bh[nt][0], Bh[nt][1]);
            }
        // ---- B lo fragments: hl product ----
#pragma unroll
        for (int nt = 0; nt < 8; nt++) {
            const uint32_t* bp =
                Bf + ((size_t)(chunk * 16 + wcol * 8 + nt) * 2 + 1) * 64 + lane * 2;
            Bh[nt][0] = bp[0];
            Bh[nt][1] = bp[1];
        }
#pragma unroll
        for (int ms = 0; ms < 2; ms++)
#pragma unroll
            for (int nt = 0; nt < 8; nt++)
                mma16(acc[ms][nt], Ah[ms], Bh[nt][0], Bh[nt][1]);
    }

    // ---- epilogue ----
    const int g = lane >> 2, tig = lane & 3;
#pragma unroll
    for (int ms = 0; ms < 2; ms++) {
        float ss0 = 0.f, ss8 = 0.f;
#pragma unroll
        for (int nt = 0; nt < 8; nt++) {
            int col = wcol * 64 + nt * 8 + tig * 2;
            acc[ms][nt][0] += s_bias[col];
            acc[ms][nt][1] += s_bias[col + 1];
            acc[ms][nt][2] += s_bias[col];
            acc[ms][nt][3] += s_bias[col + 1];
            ss0 += acc[ms][nt][0] * acc[ms][nt][0] + acc[ms][nt][1] * acc[ms][nt][1];
            ss8 += acc[ms][nt][2] * acc[ms][nt][2] + acc[ms][nt][3] * acc[ms][nt][3];
        }
        ss0 += __shfl_xor_sync(0xffffffffu, ss0, 1);
        ss0 += __shfl_xor_sync(0xffffffffu, ss0, 2);
        ss8 += __shfl_xor_sync(0xffffffffu, ss8, 1);
        ss8 += __shfl_xor_sync(0xffffffffu, ss8, 2);
        if (tig == 0) {
            s_ssq[wrow * 32 + ms * 16 + g][wcol] = ss0;
            s_ssq[wrow * 32 + ms * 16 + g + 8][wcol] = ss8;
        }
    }
    __syncthreads();
#pragma unroll
    for (int ms = 0; ms < 2; ms++) {
        int lr = wrow * 32 + ms * 16 + g;
        int m0 = mtile + lr, m8 = m0 + 8;
        float inv0 = 1.0f / fmaxf(sqrtf(s_ssq[lr][0] + s_ssq[lr][1]), 1e-12f);
        float inv8 = 1.0f / fmaxf(sqrtf(s_ssq[lr + 8][0] + s_ssq[lr + 8][1]), 1e-12f);
        float pp0 = 0.f, pp8 = 0.f;
#pragma unroll
        for (int nt = 0; nt < 8; nt++) {
            int col = wcol * 64 + nt * 8 + tig * 2;
            float e0 = acc[ms][nt][0] * inv0;
            float e1 = acc[ms][nt][1] * inv0;
            float e2 = acc[ms][nt][2] * inv8;
            float e3 = acc[ms][nt][3] * inv8;
            if (LAYER == 1) {
                e0 = fmaxf(e0, 0.f); e1 = fmaxf(e1, 0.f);
                e2 = fmaxf(e2, 0.f); e3 = fmaxf(e3, 0.f);
            }
            if (m0 < n) *(float2*)(outbuf + (size_t)m0 * HIDD + col) = make_float2(e0, e1);
            if (m8 < n) *(float2*)(outbuf + (size_t)m8 * HIDD + col) = make_float2(e2, e3);
            if (LAYER == 2 && wcol == 0) {
                pp0 += e0 * s_fcw[col] + e1 * s_fcw[col + 1];
                pp8 += e2 * s_fcw[col] + e3 * s_fcw[col + 1];
            }
        }
        if (LAYER == 2 && wcol == 0) {
            pp0 += __shfl_xor_sync(0xffffffffu, pp0, 1);
            pp0 += __shfl_xor_sync(0xffffffffu, pp0, 2);
            pp8 += __shfl_xor_sync(0xffffffffu, pp8, 1);
            pp8 += __shfl_xor_sync(0xffffffffu, pp8, 2);
            if (tig == 0) {
                float fb0 = fcb[0];
                if (m0 < n) predout[m0] = pp0 + fb0;
                if (m8 < n) predout[m8] = pp8 + fb0;
            }
        }
    }
}

// ---------------- launch ----------------------------------------------------
extern "C" void kernel_launch(void* const* d_in, const int* in_sizes, int n_in,
                              void* d_out, int out_size) {
    const float* x = (const float*)d_in[0];
    const int* ei = (const int*)d_in[1];
    const float* W1l = (const float*)d_in[2];
    const float* b1l = (const float*)d_in[3];
    const float* W1r = (const float*)d_in[4];
    const float* gamma = (const float*)d_in[5];
    const float* beta = (const float*)d_in[6];
    const float* W2l = (const float*)d_in[7];
    const float* b2l = (const float*)d_in[8];
    const float* W2r = (const float*)d_in[9];
    const float* fcW = (const float*)d_in[10];
    const float* fcb = (const float*)d_in[11];

    const int n = in_sizes[0] / HIDD;
    const int E = in_sizes[1] / 2;
    const int* src = ei;
    const int* dst = ei + E;

    float* preds = (float*)d_out;
    float* embed = (float*)d_out + n;

    float* gmean;  cudaGetSymbolAddress((void**)&gmean, g_mean);
    float* gh0;    cudaGetSymbolAddress((void**)&gh0, g_h0);
    float* gbias2; cudaGetSymbolAddress((void**)&gbias2, g_bias2);

    const int nb = (n + 1023) / 1024;
    const int gemmg = (n + 127) / 128;

    k_zero<<<(n + 255) / 256, 256>>>(n);
    k_hist<<<(E + 255) / 256, 256>>>(dst, E);
    k_scan1<<<nb, 1024>>>(n);
    k_scan2<<<1, 128>>>(nb);
    k_scan3<<<(n + 255) / 256, 256>>>(n, E);
    k_fill<<<(E + 255) / 256, 256>>>(src, dst, E);
    k_prepw<<<64, 256>>>(W1l, W1r, 0, 0);

    // layer 1
    k_agg<<<(n + 7) / 8, 256>>>(x, gmean, n, 0);
    k_mma<1><<<gemmg, 256>>>(gmean, x, b1l, nullptr, nullptr, gh0, nullptr, n);
    k_bnstat<<<(n + 255) / 256, 256>>>(gh0, n);
    k_bnfin<<<1, 128>>>(gamma, beta, n);
    k_prepw<<<64, 256>>>(W2l, W2r, 1, 1);
    k_bias2<<<1, 128>>>(b2l, W2r);

    // layer 2
    k_agg<<<(n + 7) / 8, 256>>>(gh0, gmean, n, 1);
    k_mma<2><<<gemmg, 256>>>(gmean, gh0, gbias2, fcW, fcb, embed, preds, n);
}

// round 9
// speedup vs baseline: 1.0234x; 1.0234x over previous
#include <cuda_runtime.h>
#include <math.h>
#include <stdint.h>

#define HIDD 128
#define KTOT 256
#define NMAX 100352
#define EMAX 602112

// ---------------- scratch (device globals; no allocation allowed) ----------
// NOTE: g_cnt, g_bnsum, g_bnss rely on static zero-init; every kernel_launch
// call restores them to zero after use (scan3 / bnfin), so the invariant
// "zero at entry" holds across graph replays.
__device__ int   g_cnt[NMAX];
__device__ int   g_incl[NMAX];
__device__ int   g_bsum[256];
__device__ int   g_rowptr[NMAX + 1];
__device__ int   g_wpos[NMAX];
__device__ int   g_csr[EMAX];
__device__ float g_mean[(size_t)NMAX * HIDD];
__device__ float g_h0[(size_t)NMAX * HIDD];
__device__ float g_bnsum[HIDD];
__device__ float g_bnss[HIDD];
__device__ float g_scale[HIDD];
__device__ float g_shift[HIDD];
// B fragments: [layer][ (chunk16*16+ntile)*2+part ][64]  (uint32 bf16x2 pairs)
__device__ uint32_t g_Bfrag[2][16 * 16 * 2 * 64];
__device__ float g_bias2[HIDD];

// ---------------- helpers ---------------------------------------------------
__device__ __forceinline__ float bf16rd(float x) {
    float r;
    asm("{.reg .b16 t; cvt.rn.bf16.f32 t, %1; cvt.f32.bf16 %0, t;}"
        : "=f"(r) : "f"(x));
    return r;
}
// pack: e0 -> low 16 bits, e1 -> high 16 bits (PTX: first src = upper half)
__device__ __forceinline__ uint32_t pack2(float e0, float e1) {
    uint32_t r;
    asm("cvt.rn.bf16x2.f32 %0, %1, %2;" : "=r"(r) : "f"(e1), "f"(e0));
    return r;
}
__device__ __forceinline__ uint32_t smem_u32(const void* p) {
    uint32_t a;
    asm("{ .reg .u64 t; cvta.to.shared.u64 t, %1; cvt.u32.u64 %0, t; }"
        : "=r"(a) : "l"(p));
    return a;
}
__device__ __forceinline__ void ldm4(uint32_t* r, uint32_t addr) {
    asm volatile(
        "ldmatrix.sync.aligned.m8n8.x4.shared.b16 {%0,%1,%2,%3}, [%4];"
        : "=r"(r[0]), "=r"(r[1]), "=r"(r[2]), "=r"(r[3]) : "r"(addr));
}
__device__ __forceinline__ void mma16(float* c, const uint32_t* a, uint32_t b0,
                                      uint32_t b1) {
    asm volatile(
        "mma.sync.aligned.m16n8k16.row.col.f32.bf16.bf16.f32 "
        "{%0,%1,%2,%3},{%4,%5,%6,%7},{%8,%9},{%0,%1,%2,%3};"
        : "+f"(c[0]), "+f"(c[1]), "+f"(c[2]), "+f"(c[3])
        : "r"(a[0]), "r"(a[1]), "r"(a[2]), "r"(a[3]), "r"(b0), "r"(b1));
}

// ---------------- setup kernels ---------------------------------------------
__global__ void k_hist(const int* __restrict__ dst, int E) {
    int e = blockIdx.x * blockDim.x + threadIdx.x;
    if (e < E) atomicAdd(&g_cnt[dst[e]], 1);
}
__global__ void k_scan1(int n) {
    __shared__ int s[1024];
    int t = threadIdx.x;
    int i = blockIdx.x * 1024 + t;
    int v = (i < n) ? g_cnt[i] : 0;
    s[t] = v;
    __syncthreads();
    for (int off = 1; off < 1024; off <<= 1) {
        int x = (t >= off) ? s[t - off] : 0;
        __syncthreads();
        s[t] += x;
        __syncthreads();
    }
    if (i < n) g_incl[i] = s[t];
    if (t == 1023) g_bsum[blockIdx.x] = s[1023];
}
// scan2+scan3 fused: each block redundantly scans <=128 block sums.
// Also re-zeroes g_cnt for the next call.
__global__ void k_scan3(int n, int E, int nb) {
    __shared__ int sb[128];
    int t = threadIdx.x;  // 256 threads
    if (t < 128) sb[t] = (t < nb) ? g_bsum[t] : 0;
    __syncthreads();
    for (int off = 1; off < 128; off <<= 1) {
        int x = 0;
        if (t < 128 && t >= off) x = sb[t - off];
        __syncthreads();
        if (t < 128) sb[t] += x;
        __syncthreads();
    }
    int i = blockIdx.x * blockDim.x + t;
    if (i < n) {
        int blk = i >> 10;
        int boff = (blk == 0) ? 0 : sb[blk - 1];
        int excl = g_incl[i] - g_cnt[i] + boff;
        g_rowptr[i] = excl;
        g_wpos[i] = excl;
        g_cnt[i] = 0;  // restore static-zero invariant
        if (i == 0) g_rowptr[n] = E;
    }
}
__global__ void k_fill(const int* __restrict__ src, const int* __restrict__ dst, int E) {
    int e = blockIdx.x * blockDim.x + threadIdx.x;
    if (e < E) {
        int d = dst[e];
        int p = atomicAdd(&g_wpos[d], 1);
        g_csr[p] = src[e];
    }
}

// weight -> bf16 hi/lo b-fragments for m16n8k16 row.col
__global__ void k_prepw(const float* __restrict__ Wl, const float* __restrict__ Wr,
                        int layer, int useScale) {
    int idx = blockIdx.x * 256 + threadIdx.x;  // 16384 total
    int reg = idx & 1;
    int lane = (idx >> 1) & 31;
    int ntile = (idx >> 6) & 15;
    int chunk = idx >> 10;
    int tig = lane & 3, gcol = lane >> 2;
    int nn = ntile * 8 + gcol;
    int k0 = chunk * 16 + reg * 8 + tig * 2;
    int k1 = k0 + 1;
    float w0 = (k0 < HIDD) ? Wl[k0 * HIDD + nn] : Wr[(k0 - HIDD) * HIDD + nn];
    float w1 = (k1 < HIDD) ? Wl[k1 * HIDD + nn] : Wr[(k1 - HIDD) * HIDD + nn];
    if (useScale && k0 >= HIDD) {
        w0 *= g_scale[k0 - HIDD];
        w1 *= g_scale[k1 - HIDD];
    }
    float h0 = bf16rd(w0), h1 = bf16rd(w1);
    int base = ((chunk * 16 + ntile) * 2) * 64 + lane * 2 + reg;
    g_Bfrag[layer][base] = pack2(w0, w1);
    g_Bfrag[layer][base + 64] = pack2(w0 - h0, w1 - h1);
}

// BN finalize + bias2 fused. Re-zeroes g_bnsum/g_bnss for the next call.
__global__ void k_bnfin(const float* __restrict__ gamma, const float* __restrict__ beta,
                        const float* __restrict__ b2l, const float* __restrict__ W2r,
                        int n) {
    __shared__ float sh[HIDD];
    int c = threadIdx.x;  // 128 threads
    float mu = g_bnsum[c] / (float)n;
    float var = g_bnss[c] / (float)n - mu * mu;
    float sc = gamma[c] * rsqrtf(var + 1e-5f);
    float shf = beta[c] - mu * sc;
    g_scale[c] = sc;
    g_shift[c] = shf;
    sh[c] = shf;
    g_bnsum[c] = 0.f;
    g_bnss[c] = 0.f;
    __syncthreads();
    float s = b2l[c];
    for (int j = 0; j < HIDD; j++) s += sh[j] * W2r[j * HIDD + c];
    g_bias2[c] = s;
}

// ---------------- aggregation: one warp per node, 4-way unroll --------------
__global__ void k_agg(const float* __restrict__ feat, float* __restrict__ outm,
                      int n, int layer2) {
    int w = (blockIdx.x * blockDim.x + threadIdx.x) >> 5;
    int lane = threadIdx.x & 31;
    if (w >= n) return;
    int r0 = g_rowptr[w], r1 = g_rowptr[w + 1];
    const float4* f4 = (const float4*)feat;
    float4 a = make_float4(0.f, 0.f, 0.f, 0.f);
    int j = r0;
    for (; j + 3 < r1; j += 4) {
        int s0 = g_csr[j];
        int s1 = g_csr[j + 1];
        int s2 = g_csr[j + 2];
        int s3 = g_csr[j + 3];
        float4 v0 = f4[(size_t)s0 * 32 + lane];
        float4 v1 = f4[(size_t)s1 * 32 + lane];
        float4 v2 = f4[(size_t)s2 * 32 + lane];
        float4 v3 = f4[(size_t)s3 * 32 + lane];
        a.x += v0.x + v1.x + v2.x + v3.x;
        a.y += v0.y + v1.y + v2.y + v3.y;
        a.z += v0.z + v1.z + v2.z + v3.z;
        a.w += v0.w + v1.w + v2.w + v3.w;
    }
    for (; j < r1; j++) {
        int s0 = g_csr[j];
        float4 v0 = f4[(size_t)s0 * 32 + lane];
        a.x += v0.x; a.y += v0.y; a.z += v0.z; a.w += v0.w;
    }
    int deg = r1 - r0;
    float inv = (deg > 0) ? 1.f / (float)deg : 0.f;
    float4 m = make_float4(a.x * inv, a.y * inv, a.z * inv, a.w * inv);
    if (layer2) {
        if (deg > 0) {
            float4 sc = *(const float4*)(g_scale + lane * 4);
            float4 sh = *(const float4*)(g_shift + lane * 4);
            m.x = m.x * sc.x + sh.x; m.y = m.y * sc.y + sh.y;
            m.z = m.z * sc.z + sh.z; m.w = m.w * sc.w + sh.w;
        } else {
            m = make_float4(0.f, 0.f, 0.f, 0.f);
        }
    }
    ((float4*)outm)[(size_t)w * 32 + lane] = m;
}

// ---------------- GEMM via bf16 m16n8k16 mma (3-term compensation) ----------
// Block: 128 rows x 128 cols x K=256, 256 threads = 8 warps (4 mrow x 2 ncol).
// LAYER 1 additionally accumulates BN column sums (fused bnstat).
template <int LAYER>
__global__ __launch_bounds__(256, 2) void k_mma(
    const float* __restrict__ meanbuf, const float* __restrict__ featbuf,
    const float* __restrict__ bias, const float* __restrict__ fcW,
    const float* __restrict__ fcb, float* __restrict__ outbuf,
    float* __restrict__ predout, int n) {
    __shared__ __align__(16) uint32_t sA[2][2][128 * 12];  // [buf][part][row*12+pair]
    __shared__ float s_bias[128];
    __shared__ float s_fcw[64];
    __shared__ float s_ssq[128][2];
    __shared__ float bnS[128];
    __shared__ float bnQ[128];

    const int t = threadIdx.x;
    const int wid = t >> 5, lane = t & 31;
    const int wrow = wid >> 1, wcol = wid & 1;
    const int mtile = blockIdx.x * 128;

    if (t < 128) {
        s_bias[t] = bias[t];
        if (LAYER == 1) { bnS[t] = 0.f; bnQ[t] = 0.f; }
    }
    if (LAYER == 2 && t < 64) s_fcw[t] = fcW[t];

    float acc[2][8][4];
#pragma unroll
    for (int ms = 0; ms < 2; ms++)
#pragma unroll
        for (int nt = 0; nt < 8; nt++)
#pragma unroll
            for (int j = 0; j < 4; j++) acc[ms][nt][j] = 0.f;

    const uint32_t* __restrict__ Bf = g_Bfrag[LAYER - 1];

    const int srow = t >> 1;       // staged row (0..127)
    const int kh = t & 1;          // k half (0 or 1) -> 8 floats
    const uint32_t sAb = smem_u32(&sA[0][0][0]);
    const int lrow = lane & 15;
    const int kpair = (lane >> 4) * 4;  // uint32 offset for k 8..15 matrices

    // prefetch chunk 0
    float4 av0 = make_float4(0.f, 0.f, 0.f, 0.f), av1 = av0;
    {
        int m = mtile + srow;
        if (m < n) {
            const float* p = meanbuf + (size_t)m * HIDD + kh * 8;
            av0 = *(const float4*)p;
            av1 = *(const float4*)(p + 4);
        }
    }

    for (int chunk = 0; chunk < 16; chunk++) {
        const int buf = chunk & 1;
        // ---- stage A chunk (all 256 threads) ----
        {
            float f[8] = {av0.x, av0.y, av0.z, av0.w, av1.x, av1.y, av1.z, av1.w};
            uint32_t hp[4], lp[4];
#pragma unroll
            for (int p = 0; p < 4; p++) {
                float e0 = f[2 * p], e1 = f[2 * p + 1];
                float h0 = bf16rd(e0), h1 = bf16rd(e1);
                hp[p] = pack2(e0, e1);
                lp[p] = pack2(e0 - h0, e1 - h1);
            }
            uint32_t* d0 = &sA[buf][0][srow * 12 + kh * 4];
            uint32_t* d1 = &sA[buf][1][srow * 12 + kh * 4];
            *(uint4*)d0 = make_uint4(hp[0], hp[1], hp[2], hp[3]);
            *(uint4*)d1 = make_uint4(lp[0], lp[1], lp[2], lp[3]);
        }
        __syncthreads();
        // ---- prefetch next chunk ----
        if (chunk < 15) {
            int c1 = chunk + 1;
            const float* src = (c1 < 8) ? meanbuf : featbuf;
            int kc = (c1 & 7) * 16 + kh * 8;
            int m = mtile + srow;
            if (m < n) {
                const float* p = src + (size_t)m * HIDD + kc;
                av0 = *(const float4*)p;
                av1 = *(const float4*)(p + 4);
            } else {
                av0 = make_float4(0.f, 0.f, 0.f, 0.f);
                av1 = av0;
            }
        }
        // ---- A fragments via ldmatrix ----
        uint32_t Ah[2][4], Al[2][4];
#pragma unroll
        for (int ms = 0; ms < 2; ms++) {
            int r = wrow * 32 + ms * 16 + lrow;
            uint32_t off = (uint32_t)(r * 12 + kpair) * 4u;
            ldm4(Ah[ms], sAb + buf * 12288u + off);
            ldm4(Al[ms], sAb + buf * 12288u + 6144u + off);
        }
        // ---- B hi fragments: hh + lh products ----
        uint32_t Bh[8][2];
#pragma unroll
        for (int nt = 0; nt < 8; nt++) {
            const uint32_t* bp =
                Bf + ((size_t)(chunk * 16 + wcol * 8 + nt) * 2) * 64 + lane * 2;
            Bh[nt][0] = bp[0];
            Bh[nt][1] = bp[1];
        }
#pragma unroll
        for (int ms = 0; ms < 2; ms++)
#pragma unroll
            for (int nt = 0; nt < 8; nt++) {
                mma16(acc[ms][nt], Ah[ms], Bh[nt][0], Bh[nt][1]);
                mma16(acc[ms][nt], Al[ms], Bh[nt][0], Bh[nt][1]);
            }
        // ---- B lo fragments: hl product ----
#pragma unroll
        for (int nt = 0; nt < 8; nt++) {
            const uint32_t* bp =
                Bf + ((size_t)(chunk * 16 + wcol * 8 + nt) * 2 + 1) * 64 + lane * 2;
            Bh[nt][0] = bp[0];
            Bh[nt][1] = bp[1];
        }
#pragma unroll
        for (int ms = 0; ms < 2; ms++)
#pragma unroll
            for (int nt = 0; nt < 8; nt++)
                mma16(acc[ms][nt], Ah[ms], Bh[nt][0], Bh[nt][1]);
    }

    // ---- epilogue ----
    const int g = lane >> 2, tig = lane & 3;
#pragma unroll
    for (int ms = 0; ms < 2; ms++) {
        float ss0 = 0.f, ss8 = 0.f;
#pragma unroll
        for (int nt = 0; nt < 8; nt++) {
            int col = wcol * 64 + nt * 8 + tig * 2;
            acc[ms][nt][0] += s_bias[col];
            acc[ms][nt][1] += s_bias[col + 1];
            acc[ms][nt][2] += s_bias[col];
            acc[ms][nt][3] += s_bias[col + 1];
            ss0 += acc[ms][nt][0] * acc[ms][nt][0] + acc[ms][nt][1] * acc[ms][nt][1];
            ss8 += acc[ms][nt][2] * acc[ms][nt][2] + acc[ms][nt][3] * acc[ms][nt][3];
        }
        ss0 += __shfl_xor_sync(0xffffffffu, ss0, 1);
        ss0 += __shfl_xor_sync(0xffffffffu, ss0, 2);
        ss8 += __shfl_xor_sync(0xffffffffu, ss8, 1);
        ss8 += __shfl_xor_sync(0xffffffffu, ss8, 2);
        if (tig == 0) {
            s_ssq[wrow * 32 + ms * 16 + g][wcol] = ss0;
            s_ssq[wrow * 32 + ms * 16 + g + 8][wcol] = ss8;
        }
    }
    __syncthreads();
#pragma unroll
    for (int ms = 0; ms < 2; ms++) {
        int lr = wrow * 32 + ms * 16 + g;
        int m0 = mtile + lr, m8 = m0 + 8;
        float inv0 = 1.0f / fmaxf(sqrtf(s_ssq[lr][0] + s_ssq[lr][1]), 1e-12f);
        float inv8 = 1.0f / fmaxf(sqrtf(s_ssq[lr + 8][0] + s_ssq[lr + 8][1]), 1e-12f);
        float pp0 = 0.f, pp8 = 0.f;
#pragma unroll
        for (int nt = 0; nt < 8; nt++) {
            int col = wcol * 64 + nt * 8 + tig * 2;
            float e0 = acc[ms][nt][0] * inv0;
            float e1 = acc[ms][nt][1] * inv0;
            float e2 = acc[ms][nt][2] * inv8;
            float e3 = acc[ms][nt][3] * inv8;
            if (LAYER == 1) {
                e0 = fmaxf(e0, 0.f); e1 = fmaxf(e1, 0.f);
                e2 = fmaxf(e2, 0.f); e3 = fmaxf(e3, 0.f);
            }
            if (m0 < n) *(float2*)(outbuf + (size_t)m0 * HIDD + col) = make_float2(e0, e1);
            if (m8 < n) *(float2*)(outbuf + (size_t)m8 * HIDD + col) = make_float2(e2, e3);
            if (LAYER == 1) {
                // fused BN column sums (guard out-of-range rows)
                float a0 = (m0 < n) ? e0 : 0.f;
                float a1 = (m0 < n) ? e1 : 0.f;
                float a2 = (m8 < n) ? e2 : 0.f;
                float a3 = (m8 < n) ? e3 : 0.f;
                float sc0 = a0 + a2, sc1 = a1 + a3;
                float qc0 = a0 * a0 + a2 * a2, qc1 = a1 * a1 + a3 * a3;
#pragma unroll
                for (int o = 4; o < 32; o <<= 1) {
                    sc0 += __shfl_xor_sync(0xffffffffu, sc0, o);
                    sc1 += __shfl_xor_sync(0xffffffffu, sc1, o);
                    qc0 += __shfl_xor_sync(0xffffffffu, qc0, o);
                    qc1 += __shfl_xor_sync(0xffffffffu, qc1, o);
                }
                if (g == 0) {
                    atomicAdd(&bnS[col], sc0);
                    atomicAdd(&bnS[col + 1], sc1);
                    atomicAdd(&bnQ[col], qc0);
                    atomicAdd(&bnQ[col + 1], qc1);
                }
            }
            if (LAYER == 2 && wcol == 0) {
                pp0 += e0 * s_fcw[col] + e1 * s_fcw[col + 1];
                pp8 += e2 * s_fcw[col] + e3 * s_fcw[col + 1];
            }
        }
        if (LAYER == 2 && wcol == 0) {
            pp0 += __shfl_xor_sync(0xffffffffu, pp0, 1);
            pp0 += __shfl_xor_sync(0xffffffffu, pp0, 2);
            pp8 += __shfl_xor_sync(0xffffffffu, pp8, 1);
            pp8 += __shfl_xor_sync(0xffffffffu, pp8, 2);
            if (tig == 0) {
                float fb0 = fcb[0];
                if (m0 < n) predout[m0] = pp0 + fb0;
                if (m8 < n) predout[m8] = pp8 + fb0;
            }
        }
    }
    if (LAYER == 1) {
        __syncthreads();
        if (t < 128) {
            atomicAdd(&g_bnsum[t], bnS[t]);
            atomicAdd(&g_bnss[t], bnQ[t]);
        }
    }
}

// ---------------- launch ----------------------------------------------------
extern "C" void kernel_launch(void* const* d_in, const int* in_sizes, int n_in,
                              void* d_out, int out_size) {
    const float* x = (const float*)d_in[0];
    const int* ei = (const int*)d_in[1];
    const float* W1l = (const float*)d_in[2];
    const float* b1l = (const float*)d_in[3];
    const float* W1r = (const float*)d_in[4];
    const float* gamma = (const float*)d_in[5];
    const float* beta = (const float*)d_in[6];
    const float* W2l = (const float*)d_in[7];
    const float* b2l = (const float*)d_in[8];
    const float* W2r = (const float*)d_in[9];
    const float* fcW = (const float*)d_in[10];
    const float* fcb = (const float*)d_in[11];

    const int n = in_sizes[0] / HIDD;
    const int E = in_sizes[1] / 2;
    const int* src = ei;
    const int* dst = ei + E;

    float* preds = (float*)d_out;
    float* embed = (float*)d_out + n;

    float* gmean;  cudaGetSymbolAddress((void**)&gmean, g_mean);
    float* gh0;    cudaGetSymbolAddress((void**)&gh0, g_h0);
    float* gbias2; cudaGetSymbolAddress((void**)&gbias2, g_bias2);

    const int nb = (n + 1023) / 1024;
    const int gemmg = (n + 127) / 128;

    k_hist<<<(E + 255) / 256, 256>>>(dst, E);
    k_scan1<<<nb, 1024>>>(n);
    k_scan3<<<(n + 255) / 256, 256>>>(n, E, nb);
    k_fill<<<(E + 255) / 256, 256>>>(src, dst, E);
    k_prepw<<<64, 256>>>(W1l, W1r, 0, 0);

    // layer 1
    k_agg<<<(n + 7) / 8, 256>>>(x, gmean, n, 0);
    k_mma<1><<<gemmg, 256>>>(gmean, x, b1l, nullptr, nullptr, gh0, nullptr, n);
    k_bnfin<<<1, 128>>>(gamma, beta, b2l, W2r, n);
    k_prepw<<<64, 256>>>(W2l, W2r, 1, 1);

    // layer 2
    k_agg<<<(n + 7) / 8, 256>>>(gh0, gmean, n, 1);
    k_mma<2><<<gemmg, 256>>>(gmean, gh0, gbias2, fcW, fcb, embed, preds, n);
}